// round 8
// baseline (speedup 1.0000x reference)
#include <cuda_runtime.h>
#include <cuda_fp16.h>
#include <math.h>

#define Lnum 2
#define Dm   1024
#define Hn   16
#define HDm  64
#define Vv   50257
#define Tn   2048
#define Bn   2
#define BT   (Bn*Tn)        // 4096
#define CDm  512
#define En   8
#define Fm   4096
#define EPSf 1e-5f

// GEMM tiling
#define BM 128
#define BN 128
#define BK 32
#define SST 40                       // smem row stride (halves)
#define ARR_B (BM*SST*2)             // 10240 bytes per operand array
#define STG_B (2*ARR_B)              // 20480 bytes per stage (A + W)
#define GEMM_SMEM (2*STG_B)          // 40960

// attention tiling
#define AQT 64
#define AKT 64
#define AST 72                       // attn smem row stride (halves)
#define AARR (AKT*AST*2)             // 9216
#define ASTG (2*AARR)                // 18432 (K + V)
#define ATT_SMEM (2*ASTG)            // 36864

// ---------------- scratch (static device globals) ----------------------------
__device__ float g_x  [BT*Dm];
__device__ float g_tmp[BT*Dm];
__device__ float g_moe[BT*Dm];
__device__ float g_xf [BT*Dm];

__device__ __half g_xh [BT*Dm];
__device__ __half g_qkvh[(size_t)BT*3*Dm];
__device__ __half g_ath[BT*Dm];
__device__ __half g_hh [(size_t)BT*Fm];
__device__ __half g_xfh[BT*Dm];

__device__ __half g_inwh [(size_t)Lnum*3*Dm*Dm];
__device__ __half g_outwh[(size_t)Lnum*Dm*Dm];
__device__ __half g_headh[(size_t)Vv*Dm];
__device__ __half g_w1h  [(size_t)Lnum*2*Fm*Dm];
__device__ __half g_w2h  [(size_t)Lnum*2*Dm*Fm];

__device__ int   g_eidx2[4];   // [layer*2+slot]
__device__ float g_ew2[4];

// ---------------- helpers -----------------------------------------------------
__device__ __forceinline__ unsigned pack2h(float a, float b)
{
    __half2 t = __halves2half2(__float2half(a), __float2half(b));
    return *(unsigned*)&t;
}

#define MMAF16(d, a, b) \
    asm volatile("mma.sync.aligned.m16n8k16.row.col.f32.f16.f16.f32 " \
                 "{%0,%1,%2,%3},{%4,%5,%6,%7},{%8,%9},{%0,%1,%2,%3};\n" \
                 : "+f"(d[0]), "+f"(d[1]), "+f"(d[2]), "+f"(d[3])       \
                 : "r"(a[0]), "r"(a[1]), "r"(a[2]), "r"(a[3]),          \
                   "r"(b[0]), "r"(b[1]))

#define LDSM4(r, addr) \
    asm volatile("ldmatrix.sync.aligned.m8n8.x4.shared.b16 {%0,%1,%2,%3}, [%4];" \
                 : "=r"(r[0]), "=r"(r[1]), "=r"(r[2]), "=r"(r[3]) : "r"(addr))
#define LDSM4T(r, addr) \
    asm volatile("ldmatrix.sync.aligned.m8n8.x4.trans.shared.b16 {%0,%1,%2,%3}, [%4];" \
                 : "=r"(r[0]), "=r"(r[1]), "=r"(r[2]), "=r"(r[3]) : "r"(addr))

__device__ __forceinline__ void cpa16(unsigned dst, const void* src, int bytes)
{
    asm volatile("cp.async.cg.shared.global [%0], [%1], 16, %2;"
                 :: "r"(dst), "l"(src), "r"(bytes));
}
#define CP_COMMIT() asm volatile("cp.async.commit_group;")
#define CP_WAIT1()  asm volatile("cp.async.wait_group 1;")
#define CP_WAIT0()  asm volatile("cp.async.wait_group 0;")

// ---------------- embed (fp32 + fp16) ------------------------------------------
__global__ void k_embed(const int* __restrict__ tokens,
                        const float* __restrict__ embed_w,
                        const float* __restrict__ pos_w)
{
    int row = blockIdx.x;
    int t   = row % Tn;
    int tok = tokens[row];
    const float* e = embed_w + (long)tok * Dm;
    const float* p = pos_w   + (long)t   * Dm;
    long o = (long)row * Dm;
    for (int d = threadIdx.x; d < Dm; d += blockDim.x) {
        float v = e[d] + p[d];
        g_x[o + d]  = v;
        g_xh[o + d] = __float2half(v);
    }
}

// ---------------- weight conversion kernels ------------------------------------
__global__ void k_half(const float* __restrict__ src,
                       __half* __restrict__ dst, long n)
{
    long i = ((long)blockIdx.x * 256 + threadIdx.x) * 4;
    if (i >= n) return;
    float4 v = *(const float4*)&src[i];
    __half2 a = __halves2half2(__float2half(v.x), __float2half(v.y));
    __half2 b = __halves2half2(__float2half(v.z), __float2half(v.w));
    *(__half2*)&dst[i]   = a;
    *(__half2*)&dst[i+2] = b;
}

__global__ void k_half_exp(const float* __restrict__ src,
                           __half* __restrict__ dst, long n, int sidx)
{
    long off = (long)g_eidx2[sidx] * n;
    long i = ((long)blockIdx.x * 256 + threadIdx.x) * 4;
    if (i >= n) return;
    float4 v = *(const float4*)&src[off + i];
    __half2 a = __halves2half2(__float2half(v.x), __float2half(v.y));
    __half2 b = __halves2half2(__float2half(v.z), __float2half(v.w));
    *(__half2*)&dst[i]   = a;
    *(__half2*)&dst[i+2] = b;
}

// ---------------- GEMM v3: fp16 single-pass, cp.async pipelined ----------------
// C[M,N] = op(A[M,K] @ W[N,K]^T + bias)
// flags: 1=GELU, 2=ACCUM(into fp32 C), 4=SCALE by g_ew2[sidx], 8=expert bias offset
__global__ void __launch_bounds__(256, 2)
k_gemm3(const __half* __restrict__ A,
        const __half* __restrict__ W,
        const float* __restrict__ bias,
        float* __restrict__ C,
        __half* __restrict__ Ch,
        int M, int N, int K, int sidx, int flags)
{
    extern __shared__ char dsm[];
    const int bm = blockIdx.y * BM, bn = blockIdx.x * BN;
    const int tid = threadIdx.x, lane = tid & 31, warp = tid >> 5;
    const int wm = warp & 1, wn = warp >> 1;
    const int g = lane >> 2, t2 = (lane & 3) * 2;
    const unsigned sbase = (unsigned)__cvta_generic_to_shared(dsm);

    if (flags & 8) bias += (long)g_eidx2[sidx] * N;
    const float alpha = (flags & 4) ? g_ew2[sidx] : 1.0f;

#define LOAD_STAGE(s, k0)                                                     \
    {                                                                         \
        unsigned st = sbase + (s) * STG_B;                                    \
        _Pragma("unroll")                                                     \
        for (int j = 0; j < 4; j++) {                                         \
            int cid = tid + j * 256;                                          \
            int arr = cid >> 9;                                               \
            int w = cid & 511;                                                \
            int r = w >> 2;                                                   \
            int q = (w & 3) * 8;                                              \
            unsigned dst = st + arr * ARR_B + (r * SST + q) * 2;              \
            const __half* src;                                                \
            int bytes = 16;                                                   \
            if (arr == 0) src = A + (long)(bm + r) * K + (k0) + q;            \
            else {                                                            \
                int nr = bn + r;                                              \
                if (nr >= N) { nr = 0; bytes = 0; }                           \
                src = W + (long)nr * K + (k0) + q;                            \
            }                                                                 \
            cpa16(dst, src, bytes);                                           \
        }                                                                     \
    }

    float acc[4][4][4] = {};

    const unsigned aRowOff = ((unsigned)(wm*64 + (lane&7) + ((lane>>3)&1)*8) * SST
                              + ((lane>>4)*8)) * 2;
    const unsigned bRowOff = ((unsigned)(wn*32 + (lane&7) + ((lane>>3)&1)*8) * SST
                              + ((lane>>4)*8)) * 2;

    const int nk = K / BK;
    LOAD_STAGE(0, 0);
    CP_COMMIT();

    for (int kt = 0; kt < nk; kt++) {
        if (kt + 1 < nk) {
            LOAD_STAGE((kt + 1) & 1, (kt + 1) * BK);
            CP_COMMIT();
            CP_WAIT1();
        } else {
            CP_WAIT0();
        }
        __syncthreads();

        unsigned stg = sbase + (kt & 1) * STG_B;
        #pragma unroll
        for (int kk = 0; kk < BK; kk += 16) {
            unsigned ah[4][4], bh[4][2];
            #pragma unroll
            for (int mf = 0; mf < 4; mf++) {
                unsigned ad = stg + aRowOff + (mf*16*SST + kk) * 2;
                LDSM4(ah[mf], ad);
            }
            #pragma unroll
            for (int nfp = 0; nfp < 2; nfp++) {
                unsigned r4[4];
                unsigned bd = stg + ARR_B + bRowOff + (nfp*16*SST + kk) * 2;
                LDSM4(r4, bd);
                bh[2*nfp][0]   = r4[0]; bh[2*nfp][1]   = r4[2];
                bh[2*nfp+1][0] = r4[1]; bh[2*nfp+1][1] = r4[3];
            }
            #pragma unroll
            for (int mf = 0; mf < 4; mf++)
                #pragma unroll
                for (int nf = 0; nf < 4; nf++)
                    MMAF16(acc[mf][nf], ah[mf], bh[nf]);
        }
        __syncthreads();
    }
#undef LOAD_STAGE

    // ---- epilogue ----
    #pragma unroll
    for (int mf = 0; mf < 4; mf++) {
        int m0 = bm + wm*64 + mf*16 + g;
        #pragma unroll
        for (int nf = 0; nf < 4; nf++) {
            int n0 = bn + wn*32 + nf*8 + t2;
            #pragma unroll
            for (int c = 0; c < 4; c++) {
                int m = m0 + (c >> 1) * 8;
                int n = n0 + (c & 1);
                if (n >= N) continue;
                float v = acc[mf][nf][c];
                if (bias) v += bias[n];
                if (flags & 1) v = 0.5f * v * (1.0f + erff(v * 0.70710678118654752f));
                v *= alpha;
                long o = (long)m * N + n;
                if (C) { if (flags & 2) C[o] += v; else C[o] = v; }
                if (Ch) Ch[o] = __float2half(v);
            }
        }
    }
}

// ---------------- flash attention v3 (fp16, cp.async) --------------------------
__global__ void __launch_bounds__(256)
k_attn_fa3()
{
    const int qt = (gridDim.x - 1) - blockIdx.x;
    const int h  = blockIdx.y, b = blockIdx.z;
    const int tid  = threadIdx.x;
    const int lane = tid & 31, warp = tid >> 5;
    const int wm = warp & 3, wn = warp >> 2;
    const int g  = lane >> 2;
    const int t2 = (lane & 3) * 2;

    extern __shared__ char dsm[];
    const unsigned sbase = (unsigned)__cvta_generic_to_shared(dsm);
    float* Omrg = (float*)dsm;
    __shared__ float sm_m[AQT], sm_l[AQT];

    const long rb3 = 3 * Dm;
    const int  t0  = qt * AQT;
    const long rowbase = (long)(b * Tn);

    // ---- stage Q (plain vector copies), load Q frags --------------------------
    #pragma unroll
    for (int j = 0; j < 2; j++) {
        int cid = tid + j * 256;
        int r = cid >> 3, q = (cid & 7) * 8;
        const __half* src = g_qkvh + (rowbase + t0 + r) * rb3 + h * HDm + q;
        *(uint4*)(dsm + (r * AST + q) * 2) = *(const uint4*)src;
    }
    __syncthreads();

    unsigned qh[4][4];
    const unsigned qRowOff = ((unsigned)(wm*16 + (lane&7) + ((lane>>3)&1)*8) * AST
                              + ((lane>>4)*8)) * 2;
    #pragma unroll
    for (int kk = 0; kk < 4; kk++) {
        unsigned qa = sbase + qRowOff + kk * 16 * 2;
        LDSM4(qh[kk], qa);
    }
    __syncthreads();

#define LOAD_KV(s, kt)                                                        \
    {                                                                         \
        unsigned st = sbase + (s) * ASTG;                                     \
        _Pragma("unroll")                                                     \
        for (int j = 0; j < 4; j++) {                                         \
            int cid = tid + j * 256;                                          \
            int arr = cid >> 9;                                               \
            int w = cid & 511;                                                \
            int r = w >> 3, q = (w & 7) * 8;                                  \
            long srow = (rowbase + (kt) * AKT + r) * rb3 + h * HDm + q        \
                        + (arr ? 2 * Dm : Dm);                                \
            cpa16(st + arr * AARR + (r * AST + q) * 2, g_qkvh + srow, 16);    \
        }                                                                     \
    }

    float oacc[8][4] = {};
    float mprev[2] = {-1e30f, -1e30f};
    float lsum [2] = {0.f, 0.f};

    const unsigned kRowOff = ((unsigned)(wn*32 + (lane&7) + ((lane>>3)&1)*8) * AST
                              + ((lane>>4)*8)) * 2;

    LOAD_KV(0, 0);
    CP_COMMIT();

    for (int kt = 0; kt <= qt; kt++) {
        if (kt < qt) {
            LOAD_KV((kt + 1) & 1, kt + 1);
            CP_COMMIT();
            CP_WAIT1();
        } else {
            CP_WAIT0();
        }
        __syncthreads();

        unsigned stg = sbase + (kt & 1) * ASTG;

        // ---- S = Q @ K^T ----
        float sacc[4][4] = {};
        #pragma unroll
        for (int kk = 0; kk < 4; kk++) {
            #pragma unroll
            for (int nfp = 0; nfp < 2; nfp++) {
                unsigned r4[4];
                unsigned kd = stg + kRowOff + (nfp*16*AST + kk*16) * 2;
                LDSM4(r4, kd);
                unsigned bh0[2] = {r4[0], r4[2]}, bh1[2] = {r4[1], r4[3]};
                MMAF16(sacc[2*nfp],   qh[kk], bh0);
                MMAF16(sacc[2*nfp+1], qh[kk], bh1);
            }
        }

        const bool diag = (kt == qt);
        #pragma unroll
        for (int nf = 0; nf < 4; nf++)
            #pragma unroll
            for (int c = 0; c < 4; c++) {
                float v = sacc[nf][c] * 0.125f;
                if (diag) {
                    int key = wn * 32 + nf * 8 + t2 + (c & 1);
                    int row = wm * 16 + g + (c >> 1) * 8;
                    if (key > row) v = -1.7e38f;
                }
                sacc[nf][c] = v;
            }

        // ---- online softmax ----
        float alpha[2];
        #pragma unroll
        for (int r = 0; r < 2; r++) {
            float rmax = -1.7e38f;
            #pragma unroll
            for (int nf = 0; nf < 4; nf++) {
                rmax = fmaxf(rmax, sacc[nf][2*r]);
                rmax = fmaxf(rmax, sacc[nf][2*r+1]);
            }
            rmax = fmaxf(rmax, __shfl_xor_sync(0xffffffffu, rmax, 1));
            rmax = fmaxf(rmax, __shfl_xor_sync(0xffffffffu, rmax, 2));
            float newm = fmaxf(mprev[r], rmax);
            alpha[r] = __expf(mprev[r] - newm);
            mprev[r] = newm;
            float ps = 0.f;
            #pragma unroll
            for (int nf = 0; nf < 4; nf++) {
                float p0 = __expf(sacc[nf][2*r]   - newm);
                float p1 = __expf(sacc[nf][2*r+1] - newm);
                sacc[nf][2*r] = p0; sacc[nf][2*r+1] = p1;
                ps += p0 + p1;
            }
            ps += __shfl_xor_sync(0xffffffffu, ps, 1);
            ps += __shfl_xor_sync(0xffffffffu, ps, 2);
            lsum[r] = lsum[r] * alpha[r] + ps;
        }
        #pragma unroll
        for (int nf = 0; nf < 8; nf++) {
            oacc[nf][0] *= alpha[0]; oacc[nf][1] *= alpha[0];
            oacc[nf][2] *= alpha[1]; oacc[nf][3] *= alpha[1];
        }

        // ---- O += P @ V  (V row-major, ldmatrix.trans) ----
        #pragma unroll
        for (int k2 = 0; k2 < 2; k2++) {
            unsigned pah[4];
            float* s0 = sacc[2*k2];
            float* s1 = sacc[2*k2+1];
            pah[0] = pack2h(s0[0], s0[1]);
            pah[1] = pack2h(s0[2], s0[3]);
            pah[2] = pack2h(s1[0], s1[1]);
            pah[3] = pack2h(s1[2], s1[3]);
            unsigned vRow = ((unsigned)(wn*32 + k2*16 + (lane&7) + ((lane>>3)&1)*8) * AST
                             + ((lane>>4)*8)) * 2;
            #pragma unroll
            for (int nfp = 0; nfp < 4; nfp++) {
                unsigned r4[4];
                unsigned vd = stg + AARR + vRow + nfp * 16 * 2;
                LDSM4T(r4, vd);
                unsigned vh0[2] = {r4[0], r4[1]}, vh1[2] = {r4[2], r4[3]};
                MMAF16(oacc[2*nfp],   pah, vh0);
                MMAF16(oacc[2*nfp+1], pah, vh1);
            }
        }
        __syncthreads();
    }
#undef LOAD_KV

    // ---- merge key-half warps, write fp16 output -------------------------------
    if (wn == 1) {
        #pragma unroll
        for (int nf = 0; nf < 8; nf++) {
            int d0 = nf * 8 + t2;
            Omrg[(wm*16 + g    ) * 64 + d0    ] = oacc[nf][0];
            Omrg[(wm*16 + g    ) * 64 + d0 + 1] = oacc[nf][1];
            Omrg[(wm*16 + g + 8) * 64 + d0    ] = oacc[nf][2];
            Omrg[(wm*16 + g + 8) * 64 + d0 + 1] = oacc[nf][3];
        }
        if ((lane & 3) == 0) {
            sm_m[wm*16 + g    ] = mprev[0];
            sm_m[wm*16 + g + 8] = mprev[1];
            sm_l[wm*16 + g    ] = lsum[0];
            sm_l[wm*16 + g + 8] = lsum[1];
        }
    }
    __syncthreads();
    if (wn == 0) {
        #pragma unroll
        for (int r = 0; r < 2; r++) {
            int rl = wm*16 + g + 8*r;
            float m1 = sm_m[rl], l1 = sm_l[rl];
            float m  = fmaxf(mprev[r], m1);
            float a0 = __expf(mprev[r] - m);
            float a1 = __expf(m1 - m);
            float inv = 1.0f / (lsum[r] * a0 + l1 * a1);
            long orow = ((long)(b * Tn + t0 + rl)) * Dm + h * HDm;
            #pragma unroll
            for (int nf = 0; nf < 8; nf++) {
                int d0 = nf * 8 + t2;
                float v0 = (oacc[nf][2*r]   * a0 + Omrg[rl*64 + d0    ] * a1) * inv;
                float v1 = (oacc[nf][2*r+1] * a0 + Omrg[rl*64 + d0 + 1] * a1) * inv;
                g_ath[orow + d0]     = __float2half(v0);
                g_ath[orow + d0 + 1] = __float2half(v1);
            }
        }
    }
}

// ---------------- residual add + LayerNorm (+ fp16 out) ------------------------
__global__ void k_add_ln(const float* __restrict__ x,
                         const float* __restrict__ y,
                         const float* __restrict__ g,
                         const float* __restrict__ bta,
                         float* __restrict__ out,
                         __half* __restrict__ oh)
{
    int row = blockIdx.x;
    int tid = threadIdx.x;
    __shared__ float buf[Dm];
    __shared__ float red[256];

    float psum = 0.f;
    for (int i = tid; i < Dm; i += 256) {
        float v = x[(long)row * Dm + i];
        if (y) v += y[(long)row * Dm + i];
        buf[i] = v;
        psum += v;
    }
    red[tid] = psum; __syncthreads();
    for (int s = 128; s > 0; s >>= 1) {
        if (tid < s) red[tid] += red[tid + s];
        __syncthreads();
    }
    float mu = red[0] * (1.0f / Dm); __syncthreads();

    float pvar = 0.f;
    for (int i = tid; i < Dm; i += 256) {
        float dv = buf[i] - mu;
        pvar += dv * dv;
    }
    red[tid] = pvar; __syncthreads();
    for (int s = 128; s > 0; s >>= 1) {
        if (tid < s) red[tid] += red[tid + s];
        __syncthreads();
    }
    float rstd = rsqrtf(red[0] * (1.0f / Dm) + EPSf); __syncthreads();

    for (int i = tid; i < Dm; i += 256) {
        float v = (buf[i] - mu) * rstd * g[i] + bta[i];
        long o = (long)row * Dm + i;
        out[o] = v;
        oh[o]  = __float2half(v);
    }
}

// ---------------- router -------------------------------------------------------
__global__ void k_router(const float* __restrict__ c_states,
                         const float* __restrict__ rw,
                         const float* __restrict__ rb, int layer)
{
    int tid = threadIdx.x;
    __shared__ float cm[CDm];
    __shared__ float lg[En];

    for (int d = tid; d < CDm; d += 256) {
        float s = 0.f;
        for (int r = 0; r < 64; r++) s += c_states[(long)r * CDm + d];
        cm[d] = s * (1.0f / 64.0f);
    }
    __syncthreads();
    if (tid < En) {
        float s = 0.f;
        const float* w = rw + (long)tid * CDm;
        for (int d = 0; d < CDm; d++) s += w[d] * cm[d];
        lg[tid] = s + rb[tid];
    }
    __syncthreads();
    if (tid == 0) {
        float mx = lg[0];
        for (int e = 1; e < En; e++) mx = fmaxf(mx, lg[e]);
        float p[En], sum = 0.f;
        for (int e = 0; e < En; e++) { p[e] = expf(lg[e] - mx); sum += p[e]; }
        for (int e = 0; e < En; e++) p[e] /= sum;
        int i0 = 0;
        for (int e = 1; e < En; e++) if (p[e] > p[i0]) i0 = e;
        int i1 = (i0 == 0) ? 1 : 0;
        for (int e = 0; e < En; e++) if (e != i0 && p[e] > p[i1]) i1 = e;
        float ws = p[i0] + p[i1];
        g_eidx2[layer*2 + 0] = i0; g_eidx2[layer*2 + 1] = i1;
        g_ew2[layer*2 + 0] = p[i0] / ws; g_ew2[layer*2 + 1] = p[i1] / ws;
    }
}

// ============================================================================
extern "C" void kernel_launch(void* const* d_in, const int* in_sizes, int n_in,
                              void* d_out, int out_size)
{
    const int*   tokens   = (const int*)  d_in[0];
    const float* c_states = (const float*)d_in[1];
    const float* embed_w  = (const float*)d_in[2];
    const float* pos_w    = (const float*)d_in[3];
    const float* in_w     = (const float*)d_in[4];
    const float* in_b     = (const float*)d_in[5];
    const float* out_w    = (const float*)d_in[6];
    const float* out_b    = (const float*)d_in[7];
    const float* ln_a_g   = (const float*)d_in[8];
    const float* ln_a_b   = (const float*)d_in[9];
    const float* router_w = (const float*)d_in[10];
    const float* router_b = (const float*)d_in[11];
    const float* e_w1     = (const float*)d_in[12];
    const float* e_b1     = (const float*)d_in[13];
    const float* e_w2     = (const float*)d_in[14];
    const float* e_b2     = (const float*)d_in[15];
    const float* ln_m_g   = (const float*)d_in[16];
    const float* ln_m_b   = (const float*)d_in[17];
    const float* ln_f_g   = (const float*)d_in[18];
    const float* ln_f_b   = (const float*)d_in[19];
    const float* head_w   = (const float*)d_in[20];
    float* out = (float*)d_out;

    cudaFuncSetAttribute(k_gemm3,    cudaFuncAttributeMaxDynamicSharedMemorySize, GEMM_SMEM);
    cudaFuncSetAttribute(k_attn_fa3, cudaFuncAttributeMaxDynamicSharedMemorySize, ATT_SMEM);

    float *p_x, *p_tmp, *p_moe, *p_xf;
    __half *p_xh,*p_qkvh,*p_ath,*p_hh,*p_xfh;
    __half *p_inwh,*p_outwh,*p_headh,*p_w1h,*p_w2h;
    cudaGetSymbolAddress((void**)&p_x,    g_x);
    cudaGetSymbolAddress((void**)&p_tmp,  g_tmp);
    cudaGetSymbolAddress((void**)&p_moe,  g_moe);
    cudaGetSymbolAddress((void**)&p_xf,   g_xf);
    cudaGetSymbolAddress((void**)&p_xh,   g_xh);
    cudaGetSymbolAddress((void**)&p_qkvh, g_qkvh);
    cudaGetSymbolAddress((void**)&p_ath,  g_ath);
    cudaGetSymbolAddress((void**)&p_hh,   g_hh);
    cudaGetSymbolAddress((void**)&p_xfh,  g_xfh);
    cudaGetSymbolAddress((void**)&p_inwh, g_inwh);
    cudaGetSymbolAddress((void**)&p_outwh,g_outwh);
    cudaGetSymbolAddress((void**)&p_headh,g_headh);
    cudaGetSymbolAddress((void**)&p_w1h,  g_w1h);
    cudaGetSymbolAddress((void**)&p_w2h,  g_w2h);

    // ---- routers (input-independent of x) ----
    for (int l = 0; l < Lnum; l++)
        k_router<<<1, 256>>>(c_states, router_w + (long)l * En * CDm,
                             router_b + (long)l * En, l);

    // ---- weight conversions ----
    {
        long n;
        n = (long)Lnum * 3 * Dm * Dm;
        k_half<<<(unsigned)((n/4 + 255) / 256), 256>>>(in_w, p_inwh, n);
        n = (long)Lnum * Dm * Dm;
        k_half<<<(unsigned)((n/4 + 255) / 256), 256>>>(out_w, p_outwh, n);
        n = (long)Vv * Dm;
        k_half<<<(unsigned)((n/4 + 255) / 256), 256>>>(head_w, p_headh, n);
        long ne = (long)Fm * Dm;
        unsigned ge = (unsigned)((ne/4 + 255) / 256);
        for (int l = 0; l < Lnum; l++)
            for (int s = 0; s < 2; s++) {
                int sidx = l*2 + s;
                k_half_exp<<<ge, 256>>>(e_w1 + (long)l * En * Fm * Dm,
                                        p_w1h + (long)sidx * ne, ne, sidx);
                k_half_exp<<<ge, 256>>>(e_w2 + (long)l * En * Dm * Fm,
                                        p_w2h + (long)sidx * ne, ne, sidx);
            }
    }

    k_embed<<<BT, 256>>>(tokens, embed_w, pos_w);

    dim3 blk(256);
    for (int l = 0; l < Lnum; l++) {
        {   // QKV projection -> fp16 qkv
            dim3 grid((3 * Dm) / BN, BT / BM);
            k_gemm3<<<grid, blk, GEMM_SMEM>>>(
                p_xh, p_inwh + (long)l * 3 * Dm * Dm,
                in_b + (long)l * 3 * Dm,
                nullptr, p_qkvh,
                BT, 3 * Dm, Dm, 0, 0);
        }
        {   // flash attention -> fp16 attn
            dim3 grid(Tn / AQT, Hn, Bn);
            k_attn_fa3<<<grid, 256, ATT_SMEM>>>();
        }
        {   // output projection -> fp32 tmp
            dim3 grid(Dm / BN, BT / BM);
            k_gemm3<<<grid, blk, GEMM_SMEM>>>(
                p_ath, p_outwh + (long)l * Dm * Dm,
                out_b + (long)l * Dm,
                p_tmp, nullptr,
                BT, Dm, Dm, 0, 0);
        }
        k_add_ln<<<BT, 256>>>(p_x, p_tmp, ln_a_g + l * Dm, ln_a_b + l * Dm,
                              p_x, p_xh);

        for (int s = 0; s < 2; s++) {
            int sidx = l*2 + s;
            long ne = (long)Fm * Dm;
            {   // expert W1: GELU -> fp16 h
                dim3 grid(Fm / BN, BT / BM);
                k_gemm3<<<grid, blk, GEMM_SMEM>>>(
                    p_xh, p_w1h + (long)sidx * ne,
                    e_b1 + (long)l * En * Fm,
                    nullptr, p_hh,
                    BT, Fm, Dm, sidx, 1 | 8);
            }
            {   // expert W2: scale (+accum) -> fp32 moe
                dim3 grid(Dm / BN, BT / BM);
                int flags = 4 | 8 | (s == 1 ? 2 : 0);
                k_gemm3<<<grid, blk, GEMM_SMEM>>>(
                    p_hh, p_w2h + (long)sidx * ne,
                    e_b2 + (long)l * En * Dm,
                    p_moe, nullptr,
                    BT, Dm, Fm, sidx, flags);
            }
        }
        k_add_ln<<<BT, 256>>>(p_x, p_moe, ln_m_g + l * Dm, ln_m_b + l * Dm,
                              p_x, p_xh);
    }

    k_add_ln<<<BT, 256>>>(p_x, nullptr, ln_f_g, ln_f_b, p_xf, p_xfh);

    {   // LM head
        dim3 grid((Vv + BN - 1) / BN, BT / BM);
        k_gemm3<<<grid, blk, GEMM_SMEM>>>(
            p_xfh, p_headh, nullptr,
            out, nullptr,
            BT, Vv, Dm, 0, 0);
    }
}

// round 9
// speedup vs baseline: 1.0193x; 1.0193x over previous
#include <cuda_runtime.h>
#include <cuda_fp16.h>
#include <math.h>

#define Lnum 2
#define Dm   1024
#define Hn   16
#define HDm  64
#define Vv   50257
#define Tn   2048
#define Bn   2
#define BT   (Bn*Tn)        // 4096
#define CDm  512
#define En   8
#define Fm   4096
#define EPSf 1e-5f

// GEMM tiling
#define BM 128
#define BN 128
#define BK 32
#define SST 40                       // smem row stride (halves)
#define ARR_B (BM*SST*2)             // 10240 bytes per operand array
#define STG_B (2*ARR_B)              // 20480 bytes per stage (A + W)
#define GEMM_SMEM (3*STG_B)          // 61440, 3-stage

// attention tiling
#define AQT 64
#define AKT 64
#define AST 72                       // attn smem row stride (halves)
#define AARR (AKT*AST*2)             // 9216
#define ASTG (2*AARR)                // 18432 (K + V)
#define ATT_SMEM (3*ASTG)            // 55296, 3-stage

// ---------------- scratch (static device globals) ----------------------------
__device__ float g_x  [BT*Dm];
__device__ float g_tmp[BT*Dm];
__device__ float g_moe[BT*Dm];
__device__ float g_xf [BT*Dm];
__device__ float g_cb2[Lnum*Dm];

__device__ __half g_xh [BT*Dm];
__device__ __half g_qkvh[(size_t)BT*3*Dm];
__device__ __half g_ath[BT*Dm];
__device__ __half g_hh [(size_t)BT*2*Fm];
__device__ __half g_xfh[BT*Dm];

__device__ __half g_inwh [(size_t)Lnum*3*Dm*Dm];
__device__ __half g_outwh[(size_t)Lnum*Dm*Dm];
__device__ __half g_headh[(size_t)Vv*Dm];
__device__ __half g_w1h  [(size_t)Lnum*2*Fm*Dm];   // per layer: [2*Fm, Dm]
__device__ __half g_w2h  [(size_t)Lnum*Dm*2*Fm];   // per layer: [Dm, 2*Fm] (slot-interleaved K)

__device__ int   g_eidx2[4];   // [layer*2+slot]
__device__ float g_ew2[4];

// ---------------- helpers -----------------------------------------------------
__device__ __forceinline__ unsigned pack2h(float a, float b)
{
    __half2 t = __halves2half2(__float2half(a), __float2half(b));
    return *(unsigned*)&t;
}

#define MMAF16(d, a, b) \
    asm volatile("mma.sync.aligned.m16n8k16.row.col.f32.f16.f16.f32 " \
                 "{%0,%1,%2,%3},{%4,%5,%6,%7},{%8,%9},{%0,%1,%2,%3};\n" \
                 : "+f"(d[0]), "+f"(d[1]), "+f"(d[2]), "+f"(d[3])       \
                 : "r"(a[0]), "r"(a[1]), "r"(a[2]), "r"(a[3]),          \
                   "r"(b[0]), "r"(b[1]))

#define LDSM4(r, addr) \
    asm volatile("ldmatrix.sync.aligned.m8n8.x4.shared.b16 {%0,%1,%2,%3}, [%4];" \
                 : "=r"(r[0]), "=r"(r[1]), "=r"(r[2]), "=r"(r[3]) : "r"(addr))
#define LDSM4T(r, addr) \
    asm volatile("ldmatrix.sync.aligned.m8n8.x4.trans.shared.b16 {%0,%1,%2,%3}, [%4];" \
                 : "=r"(r[0]), "=r"(r[1]), "=r"(r[2]), "=r"(r[3]) : "r"(addr))

__device__ __forceinline__ void cpa16(unsigned dst, const void* src, int bytes)
{
    asm volatile("cp.async.cg.shared.global [%0], [%1], 16, %2;"
                 :: "r"(dst), "l"(src), "r"(bytes));
}
#define CP_COMMIT() asm volatile("cp.async.commit_group;")
#define CP_WAIT1()  asm volatile("cp.async.wait_group 1;")
#define CP_WAIT0()  asm volatile("cp.async.wait_group 0;")

// ---------------- embed (fp32 + fp16) ------------------------------------------
__global__ void k_embed(const int* __restrict__ tokens,
                        const float* __restrict__ embed_w,
                        const float* __restrict__ pos_w)
{
    int row = blockIdx.x;
    int t   = row % Tn;
    int tok = tokens[row];
    const float* e = embed_w + (long)tok * Dm;
    const float* p = pos_w   + (long)t   * Dm;
    long o = (long)row * Dm;
    for (int d = threadIdx.x; d < Dm; d += blockDim.x) {
        float v = e[d] + p[d];
        g_x[o + d]  = v;
        g_xh[o + d] = __float2half(v);
    }
}

// ---------------- weight conversion kernels ------------------------------------
__global__ void k_half(const float* __restrict__ src,
                       __half* __restrict__ dst, long n)
{
    long i = ((long)blockIdx.x * 256 + threadIdx.x) * 4;
    if (i >= n) return;
    float4 v = *(const float4*)&src[i];
    *(__half2*)&dst[i]   = __halves2half2(__float2half(v.x), __float2half(v.y));
    *(__half2*)&dst[i+2] = __halves2half2(__float2half(v.z), __float2half(v.w));
}

// W1 cat: dst contiguous [slot][Fm][Dm]
__global__ void k_half_exp(const float* __restrict__ src,
                           __half* __restrict__ dst, long n, int sidx)
{
    long off = (long)g_eidx2[sidx] * n;
    long i = ((long)blockIdx.x * 256 + threadIdx.x) * 4;
    if (i >= n) return;
    float4 v = *(const float4*)&src[off + i];
    *(__half2*)&dst[i]   = __halves2half2(__float2half(v.x), __float2half(v.y));
    *(__half2*)&dst[i+2] = __halves2half2(__float2half(v.z), __float2half(v.w));
}

// W2 interleave: src [Dm, Fm] of expert -> dst[n * 2Fm + slot*Fm + k]
__global__ void k_half_exp2(const float* __restrict__ src,
                            __half* __restrict__ dst, int sidx, int slot)
{
    long ne = (long)Dm * Fm;
    long off = (long)g_eidx2[sidx] * ne;
    long i = ((long)blockIdx.x * 256 + threadIdx.x) * 4;
    if (i >= ne) return;
    long n = i / Fm, k = i % Fm;
    float4 v = *(const float4*)&src[off + i];
    long o = n * (2*Fm) + slot * Fm + k;
    *(__half2*)&dst[o]   = __halves2half2(__float2half(v.x), __float2half(v.y));
    *(__half2*)&dst[o+2] = __halves2half2(__float2half(v.z), __float2half(v.w));
}

// combined W2 bias: cb2[l][n] = ew0*b2[e0][n] + ew1*b2[e1][n]
__global__ void k_cbias(const float* __restrict__ e_b2)
{
    int l = blockIdx.x;
    int n = blockIdx.y * 256 + threadIdx.x;
    int e0 = g_eidx2[2*l], e1 = g_eidx2[2*l+1];
    g_cb2[l*Dm + n] = g_ew2[2*l]   * e_b2[(long)l*En*Dm + (long)e0*Dm + n]
                    + g_ew2[2*l+1] * e_b2[(long)l*En*Dm + (long)e1*Dm + n];
}

// ---------------- GEMM v4: fp16, 3-stage cp.async, single barrier --------------
// C[M,N] = op(A[M,K] @ W[N,K]^T + bias)
// flags: 1=GELU, 16=MOE-W1 fused epilogue (per-slot expert bias + GELU + gate wt)
__global__ void __launch_bounds__(256, 2)
k_gemm4(const __half* __restrict__ A,
        const __half* __restrict__ W,
        const float* __restrict__ bias,
        float* __restrict__ C,
        __half* __restrict__ Ch,
        int M, int N, int K, int lay, int flags)
{
    extern __shared__ char dsm[];
    const int bm = blockIdx.y * BM, bn = blockIdx.x * BN;
    const int tid = threadIdx.x, lane = tid & 31, warp = tid >> 5;
    const int wm = warp & 1, wn = warp >> 1;
    const int g = lane >> 2, t2 = (lane & 3) * 2;
    const unsigned sbase = (unsigned)__cvta_generic_to_shared(dsm);

#define LOAD_STAGE(s, k0)                                                     \
    {                                                                         \
        unsigned st = sbase + (s) * STG_B;                                    \
        _Pragma("unroll")                                                     \
        for (int j = 0; j < 4; j++) {                                         \
            int cid = tid + j * 256;                                          \
            int arr = cid >> 9;                                               \
            int w = cid & 511;                                                \
            int r = w >> 2;                                                   \
            int q = (w & 3) * 8;                                              \
            unsigned dst = st + arr * ARR_B + (r * SST + q) * 2;              \
            const __half* src;                                                \
            int bytes = 16;                                                   \
            if (arr == 0) src = A + (long)(bm + r) * K + (k0) + q;            \
            else {                                                            \
                int nr = bn + r;                                              \
                if (nr >= N) { nr = 0; bytes = 0; }                           \
                src = W + (long)nr * K + (k0) + q;                            \
            }                                                                 \
            cpa16(dst, src, bytes);                                           \
        }                                                                     \
    }

    float acc[4][4][4] = {};

    const unsigned aRowOff = ((unsigned)(wm*64 + (lane&7) + ((lane>>3)&1)*8) * SST
                              + ((lane>>4)*8)) * 2;
    const unsigned bRowOff = ((unsigned)(wn*32 + (lane&7) + ((lane>>3)&1)*8) * SST
                              + ((lane>>4)*8)) * 2;

    const int nk = K / BK;
    LOAD_STAGE(0, 0);
    CP_COMMIT();
    if (nk > 1) { LOAD_STAGE(1, BK); CP_COMMIT(); }

    int s2 = 2;                       // rotating stage index for kt+2
    for (int kt = 0; kt < nk; kt++) {
        if (kt + 1 < nk) { CP_WAIT1(); } else { CP_WAIT0(); }
        __syncthreads();
        if (kt + 2 < nk) {
            LOAD_STAGE(s2, (kt + 2) * BK);
            CP_COMMIT();
        }

        int scur = s2 + 1; if (scur >= 3) scur -= 3;   // == kt%3
        unsigned stg = sbase + scur * STG_B;
        s2 = scur + 1; if (s2 >= 3) s2 -= 3;           // hmm: see note below
        // NOTE: scur must equal kt%3. kt=0 -> s2 was 2 -> scur=0 ✓; then s2=1?
        // But next iteration needs s2 == (kt+1)+2 mod 3 == kt mod 3 == scur.
        s2 = scur;

        #pragma unroll
        for (int kk = 0; kk < BK; kk += 16) {
            unsigned ah[4][4], bh[4][2];
            #pragma unroll
            for (int mf = 0; mf < 4; mf++) {
                unsigned ad = stg + aRowOff + (mf*16*SST + kk) * 2;
                LDSM4(ah[mf], ad);
            }
            #pragma unroll
            for (int nfp = 0; nfp < 2; nfp++) {
                unsigned r4[4];
                unsigned bd = stg + ARR_B + bRowOff + (nfp*16*SST + kk) * 2;
                LDSM4(r4, bd);
                bh[2*nfp][0]   = r4[0]; bh[2*nfp][1]   = r4[2];
                bh[2*nfp+1][0] = r4[1]; bh[2*nfp+1][1] = r4[3];
            }
            #pragma unroll
            for (int mf = 0; mf < 4; mf++)
                #pragma unroll
                for (int nf = 0; nf < 4; nf++)
                    MMAF16(acc[mf][nf], ah[mf], bh[nf]);
        }
    }
#undef LOAD_STAGE

    // ---- epilogue ----
    int e0 = 0, e1 = 0; float w0f = 1.f, w1f = 1.f;
    if (flags & 16) {
        e0 = g_eidx2[2*lay]; e1 = g_eidx2[2*lay+1];
        w0f = g_ew2[2*lay];  w1f = g_ew2[2*lay+1];
    }
    #pragma unroll
    for (int mf = 0; mf < 4; mf++) {
        int m0 = bm + wm*64 + mf*16 + g;
        #pragma unroll
        for (int nf = 0; nf < 4; nf++) {
            int n0 = bn + wn*32 + nf*8 + t2;
            #pragma unroll
            for (int c = 0; c < 4; c++) {
                int m = m0 + (c >> 1) * 8;
                int n = n0 + (c & 1);
                if (n >= N) continue;
                float v = acc[mf][nf][c];
                if (flags & 16) {
                    int slot = n >> 12;           // Fm = 4096
                    int ci = n & (Fm - 1);
                    v += bias[(slot ? e1 : e0) * Fm + ci];
                    v = 0.5f * v * (1.0f + erff(v * 0.70710678118654752f));
                    v *= slot ? w1f : w0f;
                } else {
                    if (bias) v += bias[n];
                    if (flags & 1) v = 0.5f * v * (1.0f + erff(v * 0.70710678118654752f));
                }
                long o = (long)m * N + n;
                if (C)  C[o]  = v;
                if (Ch) Ch[o] = __float2half(v);
            }
        }
    }
}

// ---------------- flash attention v4 (fp16, 3-stage cp.async) ------------------
__global__ void __launch_bounds__(256)
k_attn_fa4()
{
    const int qt = (gridDim.x - 1) - blockIdx.x;
    const int h  = blockIdx.y, b = blockIdx.z;
    const int tid  = threadIdx.x;
    const int lane = tid & 31, warp = tid >> 5;
    const int wm = warp & 3, wn = warp >> 2;
    const int g  = lane >> 2;
    const int t2 = (lane & 3) * 2;

    extern __shared__ char dsm[];
    const unsigned sbase = (unsigned)__cvta_generic_to_shared(dsm);
    float* Omrg = (float*)dsm;
    __shared__ float sm_m[AQT], sm_l[AQT];

    const long rb3 = 3 * Dm;
    const int  t0  = qt * AQT;
    const long rowbase = (long)(b * Tn);

    // ---- stage Q, read Q frags -----------------------------------------------
    #pragma unroll
    for (int j = 0; j < 2; j++) {
        int cid = tid + j * 256;
        int r = cid >> 3, q = (cid & 7) * 8;
        const __half* src = g_qkvh + (rowbase + t0 + r) * rb3 + h * HDm + q;
        *(uint4*)(dsm + (r * AST + q) * 2) = *(const uint4*)src;
    }
    __syncthreads();

    unsigned qh[4][4];
    const unsigned qRowOff = ((unsigned)(wm*16 + (lane&7) + ((lane>>3)&1)*8) * AST
                              + ((lane>>4)*8)) * 2;
    #pragma unroll
    for (int kk = 0; kk < 4; kk++) {
        unsigned qa = sbase + qRowOff + kk * 16 * 2;
        LDSM4(qh[kk], qa);
    }
    __syncthreads();

#define LOAD_KV(s, kt)                                                        \
    {                                                                         \
        unsigned st = sbase + (s) * ASTG;                                     \
        _Pragma("unroll")                                                     \
        for (int j = 0; j < 4; j++) {                                         \
            int cid = tid + j * 256;                                          \
            int arr = cid >> 9;                                               \
            int w = cid & 511;                                                \
            int r = w >> 3, q = (w & 7) * 8;                                  \
            long srow = (rowbase + (kt) * AKT + r) * rb3 + h * HDm + q        \
                        + (arr ? 2 * Dm : Dm);                                \
            cpa16(st + arr * AARR + (r * AST + q) * 2, g_qkvh + srow, 16);    \
        }                                                                     \
    }

    float oacc[8][4] = {};
    float mprev[2] = {-1e30f, -1e30f};
    float lsum [2] = {0.f, 0.f};

    const unsigned kRowOff = ((unsigned)(wn*32 + (lane&7) + ((lane>>3)&1)*8) * AST
                              + ((lane>>4)*8)) * 2;

    LOAD_KV(0, 0);
    CP_COMMIT();
    if (qt > 0) { LOAD_KV(1, 1); CP_COMMIT(); }

    for (int kt = 0; kt <= qt; kt++) {
        if (kt < qt) { CP_WAIT1(); } else { CP_WAIT0(); }
        __syncthreads();
        if (kt + 2 <= qt) {
            int s2 = kt + 2; s2 -= (s2 / 3) * 3;
            LOAD_KV(s2, kt + 2);
            CP_COMMIT();
        }

        int scur = kt; scur -= (scur / 3) * 3;
        unsigned stg = sbase + scur * ASTG;

        // ---- S = Q @ K^T ----
        float sacc[4][4] = {};
        #pragma unroll
        for (int kk = 0; kk < 4; kk++) {
            #pragma unroll
            for (int nfp = 0; nfp < 2; nfp++) {
                unsigned r4[4];
                unsigned kd = stg + kRowOff + (nfp*16*AST + kk*16) * 2;
                LDSM4(r4, kd);
                unsigned bh0[2] = {r4[0], r4[2]}, bh1[2] = {r4[1], r4[3]};
                MMAF16(sacc[2*nfp],   qh[kk], bh0);
                MMAF16(sacc[2*nfp+1], qh[kk], bh1);
            }
        }

        const bool diag = (kt == qt);
        #pragma unroll
        for (int nf = 0; nf < 4; nf++)
            #pragma unroll
            for (int c = 0; c < 4; c++) {
                float v = sacc[nf][c] * 0.125f;
                if (diag) {
                    int key = wn * 32 + nf * 8 + t2 + (c & 1);
                    int row = wm * 16 + g + (c >> 1) * 8;
                    if (key > row) v = -1.7e38f;
                }
                sacc[nf][c] = v;
            }

        // ---- online softmax ----
        float alpha[2];
        #pragma unroll
        for (int r = 0; r < 2; r++) {
            float rmax = -1.7e38f;
            #pragma unroll
            for (int nf = 0; nf < 4; nf++) {
                rmax = fmaxf(rmax, sacc[nf][2*r]);
                rmax = fmaxf(rmax, sacc[nf][2*r+1]);
            }
            rmax = fmaxf(rmax, __shfl_xor_sync(0xffffffffu, rmax, 1));
            rmax = fmaxf(rmax, __shfl_xor_sync(0xffffffffu, rmax, 2));
            float newm = fmaxf(mprev[r], rmax);
            alpha[r] = __expf(mprev[r] - newm);
            mprev[r] = newm;
            float ps = 0.f;
            #pragma unroll
            for (int nf = 0; nf < 4; nf++) {
                float p0 = __expf(sacc[nf][2*r]   - newm);
                float p1 = __expf(sacc[nf][2*r+1] - newm);
                sacc[nf][2*r] = p0; sacc[nf][2*r+1] = p1;
                ps += p0 + p1;
            }
            ps += __shfl_xor_sync(0xffffffffu, ps, 1);
            ps += __shfl_xor_sync(0xffffffffu, ps, 2);
            lsum[r] = lsum[r] * alpha[r] + ps;
        }
        #pragma unroll
        for (int nf = 0; nf < 8; nf++) {
            oacc[nf][0] *= alpha[0]; oacc[nf][1] *= alpha[0];
            oacc[nf][2] *= alpha[1]; oacc[nf][3] *= alpha[1];
        }

        // ---- O += P @ V ----
        #pragma unroll
        for (int k2 = 0; k2 < 2; k2++) {
            unsigned pah[4];
            float* s0 = sacc[2*k2];
            float* s1 = sacc[2*k2+1];
            pah[0] = pack2h(s0[0], s0[1]);
            pah[1] = pack2h(s0[2], s0[3]);
            pah[2] = pack2h(s1[0], s1[1]);
            pah[3] = pack2h(s1[2], s1[3]);
            unsigned vRow = ((unsigned)(wn*32 + k2*16 + (lane&7) + ((lane>>3)&1)*8) * AST
                             + ((lane>>4)*8)) * 2;
            #pragma unroll
            for (int nfp = 0; nfp < 4; nfp++) {
                unsigned r4[4];
                unsigned vd = stg + AARR + vRow + nfp * 16 * 2;
                LDSM4T(r4, vd);
                unsigned vh0[2] = {r4[0], r4[1]}, vh1[2] = {r4[2], r4[3]};
                MMAF16(oacc[2*nfp],   pah, vh0);
                MMAF16(oacc[2*nfp+1], pah, vh1);
            }
        }
    }
#undef LOAD_KV

    // ---- merge key-half warps -------------------------------------------------
    __syncthreads();
    if (wn == 1) {
        #pragma unroll
        for (int nf = 0; nf < 8; nf++) {
            int d0 = nf * 8 + t2;
            Omrg[(wm*16 + g    ) * 64 + d0    ] = oacc[nf][0];
            Omrg[(wm*16 + g    ) * 64 + d0 + 1] = oacc[nf][1];
            Omrg[(wm*16 + g + 8) * 64 + d0    ] = oacc[nf][2];
            Omrg[(wm*16 + g + 8) * 64 + d0 + 1] = oacc[nf][3];
        }
        if ((lane & 3) == 0) {
            sm_m[wm*16 + g    ] = mprev[0];
            sm_m[wm*16 + g + 8] = mprev[1];
            sm_l[wm*16 + g    ] = lsum[0];
            sm_l[wm*16 + g + 8] = lsum[1];
        }
    }
    __syncthreads();
    if (wn == 0) {
        #pragma unroll
        for (int r = 0; r < 2; r++) {
            int rl = wm*16 + g + 8*r;
            float m1 = sm_m[rl], l1 = sm_l[rl];
            float m  = fmaxf(mprev[r], m1);
            float a0 = __expf(mprev[r] - m);
            float a1 = __expf(m1 - m);
            float inv = 1.0f / (lsum[r] * a0 + l1 * a1);
            long orow = ((long)(b * Tn + t0 + rl)) * Dm + h * HDm;
            #pragma unroll
            for (int nf = 0; nf < 8; nf++) {
                int d0 = nf * 8 + t2;
                float v0 = (oacc[nf][2*r]   * a0 + Omrg[rl*64 + d0    ] * a1) * inv;
                float v1 = (oacc[nf][2*r+1] * a0 + Omrg[rl*64 + d0 + 1] * a1) * inv;
                g_ath[orow + d0]     = __float2half(v0);
                g_ath[orow + d0 + 1] = __float2half(v1);
            }
        }
    }
}

// ---------------- residual add + LayerNorm (+ fp16 out) ------------------------
__global__ void k_add_ln(const float* __restrict__ x,
                         const float* __restrict__ y,
                         const float* __restrict__ g,
                         const float* __restrict__ bta,
                         float* __restrict__ out,
                         __half* __restrict__ oh)
{
    int row = blockIdx.x;
    int tid = threadIdx.x;
    __shared__ float buf[Dm];
    __shared__ float red[256];

    float psum = 0.f;
    for (int i = tid; i < Dm; i += 256) {
        float v = x[(long)row * Dm + i];
        if (y) v += y[(long)row * Dm + i];
        buf[i] = v;
        psum += v;
    }
    red[tid] = psum; __syncthreads();
    for (int s = 128; s > 0; s >>= 1) {
        if (tid < s) red[tid] += red[tid + s];
        __syncthreads();
    }
    float mu = red[0] * (1.0f / Dm); __syncthreads();

    float pvar = 0.f;
    for (int i = tid; i < Dm; i += 256) {
        float dv = buf[i] - mu;
        pvar += dv * dv;
    }
    red[tid] = pvar; __syncthreads();
    for (int s = 128; s > 0; s >>= 1) {
        if (tid < s) red[tid] += red[tid + s];
        __syncthreads();
    }
    float rstd = rsqrtf(red[0] * (1.0f / Dm) + EPSf); __syncthreads();

    for (int i = tid; i < Dm; i += 256) {
        float v = (buf[i] - mu) * rstd * g[i] + bta[i];
        long o = (long)row * Dm + i;
        out[o] = v;
        oh[o]  = __float2half(v);
    }
}

// ---------------- router -------------------------------------------------------
__global__ void k_router(const float* __restrict__ c_states,
                         const float* __restrict__ rw,
                         const float* __restrict__ rb, int layer)
{
    int tid = threadIdx.x;
    __shared__ float cm[CDm];
    __shared__ float lg[En];

    for (int d = tid; d < CDm; d += 256) {
        float s = 0.f;
        for (int r = 0; r < 64; r++) s += c_states[(long)r * CDm + d];
        cm[d] = s * (1.0f / 64.0f);
    }
    __syncthreads();
    if (tid < En) {
        float s = 0.f;
        const float* w = rw + (long)tid * CDm;
        for (int d = 0; d < CDm; d++) s += w[d] * cm[d];
        lg[tid] = s + rb[tid];
    }
    __syncthreads();
    if (tid == 0) {
        float mx = lg[0];
        for (int e = 1; e < En; e++) mx = fmaxf(mx, lg[e]);
        float p[En], sum = 0.f;
        for (int e = 0; e < En; e++) { p[e] = expf(lg[e] - mx); sum += p[e]; }
        for (int e = 0; e < En; e++) p[e] /= sum;
        int i0 = 0;
        for (int e = 1; e < En; e++) if (p[e] > p[i0]) i0 = e;
        int i1 = (i0 == 0) ? 1 : 0;
        for (int e = 0; e < En; e++) if (e != i0 && p[e] > p[i1]) i1 = e;
        float ws = p[i0] + p[i1];
        g_eidx2[layer*2 + 0] = i0; g_eidx2[layer*2 + 1] = i1;
        g_ew2[layer*2 + 0] = p[i0] / ws; g_ew2[layer*2 + 1] = p[i1] / ws;
    }
}

// ============================================================================
extern "C" void kernel_launch(void* const* d_in, const int* in_sizes, int n_in,
                              void* d_out, int out_size)
{
    const int*   tokens   = (const int*)  d_in[0];
    const float* c_states = (const float*)d_in[1];
    const float* embed_w  = (const float*)d_in[2];
    const float* pos_w    = (const float*)d_in[3];
    const float* in_w     = (const float*)d_in[4];
    const float* in_b     = (const float*)d_in[5];
    const float* out_w    = (const float*)d_in[6];
    const float* out_b    = (const float*)d_in[7];
    const float* ln_a_g   = (const float*)d_in[8];
    const float* ln_a_b   = (const float*)d_in[9];
    const float* router_w = (const float*)d_in[10];
    const float* router_b = (const float*)d_in[11];
    const float* e_w1     = (const float*)d_in[12];
    const float* e_b1     = (const float*)d_in[13];
    const float* e_w2     = (const float*)d_in[14];
    const float* e_b2     = (const float*)d_in[15];
    const float* ln_m_g   = (const float*)d_in[16];
    const float* ln_m_b   = (const float*)d_in[17];
    const float* ln_f_g   = (const float*)d_in[18];
    const float* ln_f_b   = (const float*)d_in[19];
    const float* head_w   = (const float*)d_in[20];
    float* out = (float*)d_out;

    cudaFuncSetAttribute(k_gemm4,    cudaFuncAttributeMaxDynamicSharedMemorySize, GEMM_SMEM);
    cudaFuncSetAttribute(k_attn_fa4, cudaFuncAttributeMaxDynamicSharedMemorySize, ATT_SMEM);

    float *p_x, *p_tmp, *p_moe, *p_xf, *p_cb2;
    __half *p_xh,*p_qkvh,*p_ath,*p_hh,*p_xfh;
    __half *p_inwh,*p_outwh,*p_headh,*p_w1h,*p_w2h;
    cudaGetSymbolAddress((void**)&p_x,    g_x);
    cudaGetSymbolAddress((void**)&p_tmp,  g_tmp);
    cudaGetSymbolAddress((void**)&p_moe,  g_moe);
    cudaGetSymbolAddress((void**)&p_xf,   g_xf);
    cudaGetSymbolAddress((void**)&p_cb2,  g_cb2);
    cudaGetSymbolAddress((void**)&p_xh,   g_xh);
    cudaGetSymbolAddress((void**)&p_qkvh, g_qkvh);
    cudaGetSymbolAddress((void**)&p_ath,  g_ath);
    cudaGetSymbolAddress((void**)&p_hh,   g_hh);
    cudaGetSymbolAddress((void**)&p_xfh,  g_xfh);
    cudaGetSymbolAddress((void**)&p_inwh, g_inwh);
    cudaGetSymbolAddress((void**)&p_outwh,g_outwh);
    cudaGetSymbolAddress((void**)&p_headh,g_headh);
    cudaGetSymbolAddress((void**)&p_w1h,  g_w1h);
    cudaGetSymbolAddress((void**)&p_w2h,  g_w2h);

    // ---- routers + combined W2 bias (x-independent) ----
    for (int l = 0; l < Lnum; l++)
        k_router<<<1, 256>>>(c_states, router_w + (long)l * En * CDm,
                             router_b + (long)l * En, l);
    {
        dim3 gb(Lnum, Dm / 256);
        k_cbias<<<gb, 256>>>(e_b2);
    }

    // ---- weight conversions ----
    {
        long n;
        n = (long)Lnum * 3 * Dm * Dm;
        k_half<<<(unsigned)((n/4 + 255) / 256), 256>>>(in_w, p_inwh, n);
        n = (long)Lnum * Dm * Dm;
        k_half<<<(unsigned)((n/4 + 255) / 256), 256>>>(out_w, p_outwh, n);
        n = (long)Vv * Dm;
        k_half<<<(unsigned)((n/4 + 255) / 256), 256>>>(head_w, p_headh, n);
        long ne = (long)Fm * Dm;
        unsigned ge = (unsigned)((ne/4 + 255) / 256);
        for (int l = 0; l < Lnum; l++)
            for (int s = 0; s < 2; s++) {
                int sidx = l*2 + s;
                k_half_exp<<<ge, 256>>>(e_w1 + (long)l * En * Fm * Dm,
                                        p_w1h + (long)sidx * ne, ne, sidx);
                k_half_exp2<<<ge, 256>>>(e_w2 + (long)l * En * Dm * Fm,
                                         p_w2h + (long)l * Dm * 2 * Fm, sidx, s);
            }
    }

    k_embed<<<BT, 256>>>(tokens, embed_w, pos_w);

    dim3 blk(256);
    for (int l = 0; l < Lnum; l++) {
        {   // QKV projection -> fp16 qkv
            dim3 grid((3 * Dm) / BN, BT / BM);
            k_gemm4<<<grid, blk, GEMM_SMEM>>>(
                p_xh, p_inwh + (long)l * 3 * Dm * Dm,
                in_b + (long)l * 3 * Dm,
                nullptr, p_qkvh,
                BT, 3 * Dm, Dm, l, 0);
        }
        {   // flash attention -> fp16 attn
            dim3 grid(Tn / AQT, Hn, Bn);
            k_attn_fa4<<<grid, 256, ATT_SMEM>>>();
        }
        {   // output projection -> fp32 tmp
            dim3 grid(Dm / BN, BT / BM);
            k_gemm4<<<grid, blk, GEMM_SMEM>>>(
                p_ath, p_outwh + (long)l * Dm * Dm,
                out_b + (long)l * Dm,
                p_tmp, nullptr,
                BT, Dm, Dm, l, 0);
        }
        k_add_ln<<<BT, 256>>>(p_x, p_tmp, ln_a_g + l * Dm, ln_a_b + l * Dm,
                              p_x, p_xh);

        {   // fused MoE W1 (both experts): N = 2*Fm, GELU+gate in epilogue
            dim3 grid((2 * Fm) / BN, BT / BM);
            k_gemm4<<<grid, blk, GEMM_SMEM>>>(
                p_xh, p_w1h + (long)l * 2 * Fm * Dm,
                e_b1 + (long)l * En * Fm,
                nullptr, p_hh,
                BT, 2 * Fm, Dm, l, 16);
        }
        {   // fused MoE W2: K = 2*Fm, combined bias, single pass
            dim3 grid(Dm / BN, BT / BM);
            k_gemm4<<<grid, blk, GEMM_SMEM>>>(
                p_hh, p_w2h + (long)l * Dm * 2 * Fm,
                p_cb2 + (long)l * Dm,
                p_moe, nullptr,
                BT, Dm, 2 * Fm, l, 0);
        }
        k_add_ln<<<BT, 256>>>(p_x, p_moe, ln_m_g + l * Dm, ln_m_b + l * Dm,
                              p_x, p_xh);
    }

    k_add_ln<<<BT, 256>>>(p_x, nullptr, ln_f_g, ln_f_b, p_xf, p_xfh);

    {   // LM head
        dim3 grid((Vv + BN - 1) / BN, BT / BM);
        k_gemm4<<<grid, blk, GEMM_SMEM>>>(
            p_xfh, p_headh, nullptr,
            out, nullptr,
            BT, Vv, Dm, 0, 0);
    }
}

// round 11
// speedup vs baseline: 1.0538x; 1.0339x over previous
#include <cuda_runtime.h>
#include <cuda_fp16.h>
#include <math.h>

#define Lnum 2
#define Dm   1024
#define Hn   16
#define HDm  64
#define Vv   50257
#define Tn   2048
#define Bn   2
#define BT   (Bn*Tn)        // 4096
#define CDm  512
#define En   8
#define Fm   4096
#define EPSf 1e-5f

// GEMM tiling
#define BM 128
#define BN 128
#define BK 32
#define SST 40                       // smem row stride (halves)
#define ARR_B (BM*SST*2)             // 10240 bytes per operand array
#define STG_B (2*ARR_B)              // 20480 bytes per stage (A + W)
#define GEMM_SMEM (3*STG_B)          // 61440, 3-stage

// attention tiling
#define AQT 64
#define AKT 64
#define AST 72                       // attn smem row stride (halves)
#define AARR (AKT*AST*2)             // 9216
#define ASTG (2*AARR)                // 18432 (K + V)
#define ATT_SMEM (3*ASTG)            // 55296, 3-stage

// ---------------- scratch (static device globals) ----------------------------
__device__ float g_x  [BT*Dm];
__device__ float g_tmp[BT*Dm];
__device__ float g_moe[BT*Dm];
__device__ float g_xf [BT*Dm];
__device__ float g_cb2[Lnum*Dm];

__device__ __half g_xh [BT*Dm];
__device__ __half g_qkvh[(size_t)BT*3*Dm];
__device__ __half g_ath[BT*Dm];
__device__ __half g_hh [(size_t)BT*2*Fm];
__device__ __half g_xfh[BT*Dm];

__device__ __half g_inwh [(size_t)Lnum*3*Dm*Dm];
__device__ __half g_outwh[(size_t)Lnum*Dm*Dm];
__device__ __half g_headh[(size_t)Vv*Dm];
__device__ __half g_w1h  [(size_t)Lnum*2*Fm*Dm];   // per layer: [2*Fm, Dm]
__device__ __half g_w2h  [(size_t)Lnum*Dm*2*Fm];   // per layer: [Dm, 2*Fm] (slot-interleaved K)

__device__ int   g_eidx2[4];   // [layer*2+slot]
__device__ float g_ew2[4];

// ---------------- helpers -----------------------------------------------------
__device__ __forceinline__ unsigned pack2h(float a, float b)
{
    __half2 t = __halves2half2(__float2half(a), __float2half(b));
    return *(unsigned*)&t;
}

#define MMAF16(d, a, b) \
    asm volatile("mma.sync.aligned.m16n8k16.row.col.f32.f16.f16.f32 " \
                 "{%0,%1,%2,%3},{%4,%5,%6,%7},{%8,%9},{%0,%1,%2,%3};\n" \
                 : "+f"(d[0]), "+f"(d[1]), "+f"(d[2]), "+f"(d[3])       \
                 : "r"(a[0]), "r"(a[1]), "r"(a[2]), "r"(a[3]),          \
                   "r"(b[0]), "r"(b[1]))

#define LDSM4(r, addr) \
    asm volatile("ldmatrix.sync.aligned.m8n8.x4.shared.b16 {%0,%1,%2,%3}, [%4];" \
                 : "=r"(r[0]), "=r"(r[1]), "=r"(r[2]), "=r"(r[3]) : "r"(addr))
#define LDSM4T(r, addr) \
    asm volatile("ldmatrix.sync.aligned.m8n8.x4.trans.shared.b16 {%0,%1,%2,%3}, [%4];" \
                 : "=r"(r[0]), "=r"(r[1]), "=r"(r[2]), "=r"(r[3]) : "r"(addr))

__device__ __forceinline__ void cpa16(unsigned dst, const void* src, int bytes)
{
    asm volatile("cp.async.cg.shared.global [%0], [%1], 16, %2;"
                 :: "r"(dst), "l"(src), "r"(bytes));
}
#define CP_COMMIT() asm volatile("cp.async.commit_group;")
#define CP_WAIT1()  asm volatile("cp.async.wait_group 1;")
#define CP_WAIT0()  asm volatile("cp.async.wait_group 0;")

__device__ __forceinline__ float gelu_f(float v)
{
    return 0.5f * v * (1.0f + erff(v * 0.70710678118654752f));
}

// ---------------- embed (fp32 + fp16) ------------------------------------------
__global__ void k_embed(const int* __restrict__ tokens,
                        const float* __restrict__ embed_w,
                        const float* __restrict__ pos_w)
{
    int row = blockIdx.x;
    int t   = row % Tn;
    int tok = tokens[row];
    const float* e = embed_w + (long)tok * Dm;
    const float* p = pos_w   + (long)t   * Dm;
    long o = (long)row * Dm;
    for (int d = threadIdx.x; d < Dm; d += blockDim.x) {
        float v = e[d] + p[d];
        g_x[o + d]  = v;
        g_xh[o + d] = __float2half(v);
    }
}

// ---------------- weight conversion kernels (streaming stores) -----------------
__device__ __forceinline__ void st_half4_cs(__half* dst, float4 v)
{
    int2 p = make_int2((int)pack2h(v.x, v.y), (int)pack2h(v.z, v.w));
    __stcs(reinterpret_cast<int2*>(dst), p);
}

__global__ void k_half(const float* __restrict__ src,
                       __half* __restrict__ dst, long n)
{
    long i = ((long)blockIdx.x * 256 + threadIdx.x) * 4;
    if (i >= n) return;
    st_half4_cs(&dst[i], *(const float4*)&src[i]);
}

// W1 cat: dst contiguous [slot][Fm][Dm]
__global__ void k_half_exp(const float* __restrict__ src,
                           __half* __restrict__ dst, long n, int sidx)
{
    long off = (long)g_eidx2[sidx] * n;
    long i = ((long)blockIdx.x * 256 + threadIdx.x) * 4;
    if (i >= n) return;
    st_half4_cs(&dst[i], *(const float4*)&src[off + i]);
}

// W2 interleave: src [Dm, Fm] of expert -> dst[n * 2Fm + slot*Fm + k]
__global__ void k_half_exp2(const float* __restrict__ src,
                            __half* __restrict__ dst, int sidx, int slot)
{
    long ne = (long)Dm * Fm;
    long off = (long)g_eidx2[sidx] * ne;
    long i = ((long)blockIdx.x * 256 + threadIdx.x) * 4;
    if (i >= ne) return;
    long n = i / Fm, k = i % Fm;
    long o = n * (2*Fm) + slot * Fm + k;
    st_half4_cs(&dst[o], *(const float4*)&src[off + i]);
}

// combined W2 bias: cb2[l][n] = ew0*b2[e0][n] + ew1*b2[e1][n]
__global__ void k_cbias(const float* __restrict__ e_b2)
{
    int l = blockIdx.x;
    int n = blockIdx.y * 256 + threadIdx.x;
    int e0 = g_eidx2[2*l], e1 = g_eidx2[2*l+1];
    g_cb2[l*Dm + n] = g_ew2[2*l]   * e_b2[(long)l*En*Dm + (long)e0*Dm + n]
                    + g_ew2[2*l+1] * e_b2[(long)l*En*Dm + (long)e1*Dm + n];
}

// ---------------- GEMM v5: fp16, 3-stage, M-fast raster, safe epilogue ---------
// C[M,N] = op(A[M,K] @ W[N,K]^T + bias)
// grid: (M/BM, ceil(N/BN))  — blockIdx.x = M tile (fast) for L2 W-reuse
// flags: 1=GELU, 16=MOE-W1 fused epilogue, 32=streaming C store
__global__ void __launch_bounds__(256, 2)
k_gemm5(const __half* __restrict__ A,
        const __half* __restrict__ W,
        const float* __restrict__ bias,
        float* __restrict__ C,
        __half* __restrict__ Ch,
        int M, int N, int K, int lay, int flags)
{
    extern __shared__ char dsm[];
    const int bm = blockIdx.x * BM, bn = blockIdx.y * BN;
    const int tid = threadIdx.x, lane = tid & 31, warp = tid >> 5;
    const int wm = warp & 1, wn = warp >> 1;
    const int g = lane >> 2, t2 = (lane & 3) * 2;
    const unsigned sbase = (unsigned)__cvta_generic_to_shared(dsm);

#define LOAD_STAGE(s, k0)                                                     \
    {                                                                         \
        unsigned st = sbase + (s) * STG_B;                                    \
        _Pragma("unroll")                                                     \
        for (int j = 0; j < 4; j++) {                                         \
            int cid = tid + j * 256;                                          \
            int arr = cid >> 9;                                               \
            int w = cid & 511;                                                \
            int r = w >> 2;                                                   \
            int q = (w & 3) * 8;                                              \
            unsigned dst = st + arr * ARR_B + (r * SST + q) * 2;              \
            const __half* src;                                                \
            int bytes = 16;                                                   \
            if (arr == 0) src = A + (long)(bm + r) * K + (k0) + q;            \
            else {                                                            \
                int nr = bn + r;                                              \
                if (nr >= N) { nr = 0; bytes = 0; }                           \
                src = W + (long)nr * K + (k0) + q;                            \
            }                                                                 \
            cpa16(dst, src, bytes);                                           \
        }                                                                     \
    }

    float acc[4][4][4] = {};

    const unsigned aRowOff = ((unsigned)(wm*64 + (lane&7) + ((lane>>3)&1)*8) * SST
                              + ((lane>>4)*8)) * 2;
    const unsigned bRowOff = ((unsigned)(wn*32 + (lane&7) + ((lane>>3)&1)*8) * SST
                              + ((lane>>4)*8)) * 2;

    const int nk = K / BK;
    LOAD_STAGE(0, 0);
    CP_COMMIT();
    if (nk > 1) { LOAD_STAGE(1, BK); CP_COMMIT(); }

    int s2 = 2;                       // stage that will receive tile kt+2
    for (int kt = 0; kt < nk; kt++) {
        if (kt + 1 < nk) { CP_WAIT1(); } else { CP_WAIT0(); }
        __syncthreads();
        if (kt + 2 < nk) {
            LOAD_STAGE(s2, (kt + 2) * BK);
            CP_COMMIT();
        }

        int scur = s2 + 1; if (scur >= 3) scur -= 3;   // == kt % 3
        unsigned stg = sbase + scur * STG_B;
        s2 = scur;                                      // next load slot = (kt+3)%3

        #pragma unroll
        for (int kk = 0; kk < BK; kk += 16) {
            unsigned ah[4][4], bh[4][2];
            #pragma unroll
            for (int mf = 0; mf < 4; mf++) {
                unsigned ad = stg + aRowOff + (mf*16*SST + kk) * 2;
                LDSM4(ah[mf], ad);
            }
            #pragma unroll
            for (int nfp = 0; nfp < 2; nfp++) {
                unsigned r4[4];
                unsigned bd = stg + ARR_B + bRowOff + (nfp*16*SST + kk) * 2;
                LDSM4(r4, bd);
                bh[2*nfp][0]   = r4[0]; bh[2*nfp][1]   = r4[2];
                bh[2*nfp+1][0] = r4[1]; bh[2*nfp+1][1] = r4[3];
            }
            #pragma unroll
            for (int mf = 0; mf < 4; mf++)
                #pragma unroll
                for (int nf = 0; nf < 4; nf++)
                    MMAF16(acc[mf][nf], ah[mf], bh[nf]);
        }
    }
#undef LOAD_STAGE

    // ---- epilogue: paired values; vector store only when row stride is even ---
    int e0 = 0, e1 = 0; float w0f = 1.f, w1f = 1.f;
    if (flags & 16) {
        e0 = g_eidx2[2*lay]; e1 = g_eidx2[2*lay+1];
        w0f = g_ew2[2*lay];  w1f = g_ew2[2*lay+1];
    }
    const bool evenN = ((N & 1) == 0);
    #pragma unroll
    for (int mf = 0; mf < 4; mf++) {
        int m0 = bm + wm*64 + mf*16 + g;
        #pragma unroll
        for (int nf = 0; nf < 4; nf++) {
            int n0 = bn + wn*32 + nf*8 + t2;
            #pragma unroll
            for (int cr = 0; cr < 2; cr++) {
                int m = m0 + cr * 8;
                float v0 = acc[mf][nf][2*cr];
                float v1 = acc[mf][nf][2*cr+1];
                if (flags & 16) {
                    int slot = n0 >> 12;              // pair never crosses Fm bnd
                    int ci = n0 & (Fm - 1);
                    const float* bb = bias + (slot ? e1 : e0) * Fm;
                    float gw = slot ? w1f : w0f;
                    v0 = gelu_f(v0 + bb[ci])     * gw;
                    v1 = gelu_f(v1 + bb[ci + 1]) * gw;
                } else {
                    if (n0 < N)     v0 = bias ? v0 + bias[n0]     : v0;
                    if (n0 + 1 < N) v1 = bias ? v1 + bias[n0 + 1] : v1;
                    if (flags & 1) { v0 = gelu_f(v0); v1 = gelu_f(v1); }
                }
                long o = (long)m * N + n0;
                if (evenN && n0 + 1 < N) {
                    // o is even here (N even, n0 even) -> 8B-aligned
                    if (C) {
                        if (flags & 32)
                            __stcs(reinterpret_cast<float2*>(&C[o]),
                                   make_float2(v0, v1));
                        else
                            *reinterpret_cast<float2*>(&C[o]) = make_float2(v0, v1);
                    }
                    if (Ch)
                        *reinterpret_cast<unsigned*>(&Ch[o]) = pack2h(v0, v1);
                } else {
                    if (n0 < N) {
                        if (C) { if (flags & 32) __stcs(&C[o], v0); else C[o] = v0; }
                        if (Ch) Ch[o] = __float2half(v0);
                    }
                    if (n0 + 1 < N) {
                        if (C) { if (flags & 32) __stcs(&C[o+1], v1); else C[o+1] = v1; }
                        if (Ch) Ch[o+1] = __float2half(v1);
                    }
                }
            }
        }
    }
}

// ---------------- flash attention v4 (fp16, 3-stage cp.async) ------------------
__global__ void __launch_bounds__(256)
k_attn_fa4()
{
    const int qt = (gridDim.x - 1) - blockIdx.x;
    const int h  = blockIdx.y, b = blockIdx.z;
    const int tid  = threadIdx.x;
    const int lane = tid & 31, warp = tid >> 5;
    const int wm = warp & 3, wn = warp >> 2;
    const int g  = lane >> 2;
    const int t2 = (lane & 3) * 2;

    extern __shared__ char dsm[];
    const unsigned sbase = (unsigned)__cvta_generic_to_shared(dsm);
    float* Omrg = (float*)dsm;
    __shared__ float sm_m[AQT], sm_l[AQT];

    const long rb3 = 3 * Dm;
    const int  t0  = qt * AQT;
    const long rowbase = (long)(b * Tn);

    // ---- stage Q, read Q frags -----------------------------------------------
    #pragma unroll
    for (int j = 0; j < 2; j++) {
        int cid = tid + j * 256;
        int r = cid >> 3, q = (cid & 7) * 8;
        const __half* src = g_qkvh + (rowbase + t0 + r) * rb3 + h * HDm + q;
        *(uint4*)(dsm + (r * AST + q) * 2) = *(const uint4*)src;
    }
    __syncthreads();

    unsigned qh[4][4];
    const unsigned qRowOff = ((unsigned)(wm*16 + (lane&7) + ((lane>>3)&1)*8) * AST
                              + ((lane>>4)*8)) * 2;
    #pragma unroll
    for (int kk = 0; kk < 4; kk++) {
        unsigned qa = sbase + qRowOff + kk * 16 * 2;
        LDSM4(qh[kk], qa);
    }
    __syncthreads();

#define LOAD_KV(s, kt)                                                        \
    {                                                                         \
        unsigned st = sbase + (s) * ASTG;                                     \
        _Pragma("unroll")                                                     \
        for (int j = 0; j < 4; j++) {                                         \
            int cid = tid + j * 256;                                          \
            int arr = cid >> 9;                                               \
            int w = cid & 511;                                                \
            int r = w >> 3, q = (w & 7) * 8;                                  \
            long srow = (rowbase + (kt) * AKT + r) * rb3 + h * HDm + q        \
                        + (arr ? 2 * Dm : Dm);                                \
            cpa16(st + arr * AARR + (r * AST + q) * 2, g_qkvh + srow, 16);    \
        }                                                                     \
    }

    float oacc[8][4] = {};
    float mprev[2] = {-1e30f, -1e30f};
    float lsum [2] = {0.f, 0.f};

    const unsigned kRowOff = ((unsigned)(wn*32 + (lane&7) + ((lane>>3)&1)*8) * AST
                              + ((lane>>4)*8)) * 2;

    LOAD_KV(0, 0);
    CP_COMMIT();
    if (qt > 0) { LOAD_KV(1, 1); CP_COMMIT(); }

    for (int kt = 0; kt <= qt; kt++) {
        if (kt < qt) { CP_WAIT1(); } else { CP_WAIT0(); }
        __syncthreads();
        if (kt + 2 <= qt) {
            int s2 = kt + 2; s2 -= (s2 / 3) * 3;
            LOAD_KV(s2, kt + 2);
            CP_COMMIT();
        }

        int scur = kt; scur -= (scur / 3) * 3;
        unsigned stg = sbase + scur * ASTG;

        // ---- S = Q @ K^T ----
        float sacc[4][4] = {};
        #pragma unroll
        for (int kk = 0; kk < 4; kk++) {
            #pragma unroll
            for (int nfp = 0; nfp < 2; nfp++) {
                unsigned r4[4];
                unsigned kd = stg + kRowOff + (nfp*16*AST + kk*16) * 2;
                LDSM4(r4, kd);
                unsigned bh0[2] = {r4[0], r4[2]}, bh1[2] = {r4[1], r4[3]};
                MMAF16(sacc[2*nfp],   qh[kk], bh0);
                MMAF16(sacc[2*nfp+1], qh[kk], bh1);
            }
        }

        const bool diag = (kt == qt);
        #pragma unroll
        for (int nf = 0; nf < 4; nf++)
            #pragma unroll
            for (int c = 0; c < 4; c++) {
                float v = sacc[nf][c] * 0.125f;
                if (diag) {
                    int key = wn * 32 + nf * 8 + t2 + (c & 1);
                    int row = wm * 16 + g + (c >> 1) * 8;
                    if (key > row) v = -1.7e38f;
                }
                sacc[nf][c] = v;
            }

        // ---- online softmax ----
        float alpha[2];
        #pragma unroll
        for (int r = 0; r < 2; r++) {
            float rmax = -1.7e38f;
            #pragma unroll
            for (int nf = 0; nf < 4; nf++) {
                rmax = fmaxf(rmax, sacc[nf][2*r]);
                rmax = fmaxf(rmax, sacc[nf][2*r+1]);
            }
            rmax = fmaxf(rmax, __shfl_xor_sync(0xffffffffu, rmax, 1));
            rmax = fmaxf(rmax, __shfl_xor_sync(0xffffffffu, rmax, 2));
            float newm = fmaxf(mprev[r], rmax);
            alpha[r] = __expf(mprev[r] - newm);
            mprev[r] = newm;
            float ps = 0.f;
            #pragma unroll
            for (int nf = 0; nf < 4; nf++) {
                float p0 = __expf(sacc[nf][2*r]   - newm);
                float p1 = __expf(sacc[nf][2*r+1] - newm);
                sacc[nf][2*r] = p0; sacc[nf][2*r+1] = p1;
                ps += p0 + p1;
            }
            ps += __shfl_xor_sync(0xffffffffu, ps, 1);
            ps += __shfl_xor_sync(0xffffffffu, ps, 2);
            lsum[r] = lsum[r] * alpha[r] + ps;
        }
        #pragma unroll
        for (int nf = 0; nf < 8; nf++) {
            oacc[nf][0] *= alpha[0]; oacc[nf][1] *= alpha[0];
            oacc[nf][2] *= alpha[1]; oacc[nf][3] *= alpha[1];
        }

        // ---- O += P @ V ----
        #pragma unroll
        for (int k2 = 0; k2 < 2; k2++) {
            unsigned pah[4];
            float* s0 = sacc[2*k2];
            float* s1 = sacc[2*k2+1];
            pah[0] = pack2h(s0[0], s0[1]);
            pah[1] = pack2h(s0[2], s0[3]);
            pah[2] = pack2h(s1[0], s1[1]);
            pah[3] = pack2h(s1[2], s1[3]);
            unsigned vRow = ((unsigned)(wn*32 + k2*16 + (lane&7) + ((lane>>3)&1)*8) * AST
                             + ((lane>>4)*8)) * 2;
            #pragma unroll
            for (int nfp = 0; nfp < 4; nfp++) {
                unsigned r4[4];
                unsigned vd = stg + AARR + vRow + nfp * 16 * 2;
                LDSM4T(r4, vd);
                unsigned vh0[2] = {r4[0], r4[1]}, vh1[2] = {r4[2], r4[3]};
                MMAF16(oacc[2*nfp],   pah, vh0);
                MMAF16(oacc[2*nfp+1], pah, vh1);
            }
        }
    }
#undef LOAD_KV

    // ---- merge key-half warps -------------------------------------------------
    __syncthreads();
    if (wn == 1) {
        #pragma unroll
        for (int nf = 0; nf < 8; nf++) {
            int d0 = nf * 8 + t2;
            Omrg[(wm*16 + g    ) * 64 + d0    ] = oacc[nf][0];
            Omrg[(wm*16 + g    ) * 64 + d0 + 1] = oacc[nf][1];
            Omrg[(wm*16 + g + 8) * 64 + d0    ] = oacc[nf][2];
            Omrg[(wm*16 + g + 8) * 64 + d0 + 1] = oacc[nf][3];
        }
        if ((lane & 3) == 0) {
            sm_m[wm*16 + g    ] = mprev[0];
            sm_m[wm*16 + g + 8] = mprev[1];
            sm_l[wm*16 + g    ] = lsum[0];
            sm_l[wm*16 + g + 8] = lsum[1];
        }
    }
    __syncthreads();
    if (wn == 0) {
        #pragma unroll
        for (int r = 0; r < 2; r++) {
            int rl = wm*16 + g + 8*r;
            float m1 = sm_m[rl], l1 = sm_l[rl];
            float m  = fmaxf(mprev[r], m1);
            float a0 = __expf(mprev[r] - m);
            float a1 = __expf(m1 - m);
            float inv = 1.0f / (lsum[r] * a0 + l1 * a1);
            long orow = ((long)(b * Tn + t0 + rl)) * Dm + h * HDm;
            #pragma unroll
            for (int nf = 0; nf < 8; nf++) {
                int d0 = nf * 8 + t2;
                float v0 = (oacc[nf][2*r]   * a0 + Omrg[rl*64 + d0    ] * a1) * inv;
                float v1 = (oacc[nf][2*r+1] * a0 + Omrg[rl*64 + d0 + 1] * a1) * inv;
                *reinterpret_cast<unsigned*>(&g_ath[orow + d0]) = pack2h(v0, v1);
            }
        }
    }
}

// ---------------- residual add + LayerNorm (+ fp16 out) ------------------------
__global__ void k_add_ln(const float* __restrict__ x,
                         const float* __restrict__ y,
                         const float* __restrict__ g,
                         const float* __restrict__ bta,
                         float* __restrict__ out,
                         __half* __restrict__ oh)
{
    int row = blockIdx.x;
    int tid = threadIdx.x;
    __shared__ float buf[Dm];
    __shared__ float red[256];

    float psum = 0.f;
    for (int i = tid; i < Dm; i += 256) {
        float v = x[(long)row * Dm + i];
        if (y) v += y[(long)row * Dm + i];
        buf[i] = v;
        psum += v;
    }
    red[tid] = psum; __syncthreads();
    for (int s = 128; s > 0; s >>= 1) {
        if (tid < s) red[tid] += red[tid + s];
        __syncthreads();
    }
    float mu = red[0] * (1.0f / Dm); __syncthreads();

    float pvar = 0.f;
    for (int i = tid; i < Dm; i += 256) {
        float dv = buf[i] - mu;
        pvar += dv * dv;
    }
    red[tid] = pvar; __syncthreads();
    for (int s = 128; s > 0; s >>= 1) {
        if (tid < s) red[tid] += red[tid + s];
        __syncthreads();
    }
    float rstd = rsqrtf(red[0] * (1.0f / Dm) + EPSf); __syncthreads();

    for (int i = tid; i < Dm; i += 256) {
        float v = (buf[i] - mu) * rstd * g[i] + bta[i];
        long o = (long)row * Dm + i;
        out[o] = v;
        oh[o]  = __float2half(v);
    }
}

// ---------------- router -------------------------------------------------------
__global__ void k_router(const float* __restrict__ c_states,
                         const float* __restrict__ rw,
                         const float* __restrict__ rb, int layer)
{
    int tid = threadIdx.x;
    __shared__ float cm[CDm];
    __shared__ float lg[En];

    for (int d = tid; d < CDm; d += 256) {
        float s = 0.f;
        for (int r = 0; r < 64; r++) s += c_states[(long)r * CDm + d];
        cm[d] = s * (1.0f / 64.0f);
    }
    __syncthreads();
    if (tid < En) {
        float s = 0.f;
        const float* w = rw + (long)tid * CDm;
        for (int d = 0; d < CDm; d++) s += w[d] * cm[d];
        lg[tid] = s + rb[tid];
    }
    __syncthreads();
    if (tid == 0) {
        float mx = lg[0];
        for (int e = 1; e < En; e++) mx = fmaxf(mx, lg[e]);
        float p[En], sum = 0.f;
        for (int e = 0; e < En; e++) { p[e] = expf(lg[e] - mx); sum += p[e]; }
        for (int e = 0; e < En; e++) p[e] /= sum;
        int i0 = 0;
        for (int e = 1; e < En; e++) if (p[e] > p[i0]) i0 = e;
        int i1 = (i0 == 0) ? 1 : 0;
        for (int e = 0; e < En; e++) if (e != i0 && p[e] > p[i1]) i1 = e;
        float ws = p[i0] + p[i1];
        g_eidx2[layer*2 + 0] = i0; g_eidx2[layer*2 + 1] = i1;
        g_ew2[layer*2 + 0] = p[i0] / ws; g_ew2[layer*2 + 1] = p[i1] / ws;
    }
}

// ============================================================================
extern "C" void kernel_launch(void* const* d_in, const int* in_sizes, int n_in,
                              void* d_out, int out_size)
{
    const int*   tokens   = (const int*)  d_in[0];
    const float* c_states = (const float*)d_in[1];
    const float* embed_w  = (const float*)d_in[2];
    const float* pos_w    = (const float*)d_in[3];
    const float* in_w     = (const float*)d_in[4];
    const float* in_b     = (const float*)d_in[5];
    const float* out_w    = (const float*)d_in[6];
    const float* out_b    = (const float*)d_in[7];
    const float* ln_a_g   = (const float*)d_in[8];
    const float* ln_a_b   = (const float*)d_in[9];
    const float* router_w = (const float*)d_in[10];
    const float* router_b = (const float*)d_in[11];
    const float* e_w1     = (const float*)d_in[12];
    const float* e_b1     = (const float*)d_in[13];
    const float* e_w2     = (const float*)d_in[14];
    const float* e_b2     = (const float*)d_in[15];
    const float* ln_m_g   = (const float*)d_in[16];
    const float* ln_m_b   = (const float*)d_in[17];
    const float* ln_f_g   = (const float*)d_in[18];
    const float* ln_f_b   = (const float*)d_in[19];
    const float* head_w   = (const float*)d_in[20];
    float* out = (float*)d_out;

    cudaFuncSetAttribute(k_gemm5,    cudaFuncAttributeMaxDynamicSharedMemorySize, GEMM_SMEM);
    cudaFuncSetAttribute(k_attn_fa4, cudaFuncAttributeMaxDynamicSharedMemorySize, ATT_SMEM);

    float *p_x, *p_tmp, *p_moe, *p_xf, *p_cb2;
    __half *p_xh,*p_qkvh,*p_ath,*p_hh,*p_xfh;
    __half *p_inwh,*p_outwh,*p_headh,*p_w1h,*p_w2h;
    cudaGetSymbolAddress((void**)&p_x,    g_x);
    cudaGetSymbolAddress((void**)&p_tmp,  g_tmp);
    cudaGetSymbolAddress((void**)&p_moe,  g_moe);
    cudaGetSymbolAddress((void**)&p_xf,   g_xf);
    cudaGetSymbolAddress((void**)&p_cb2,  g_cb2);
    cudaGetSymbolAddress((void**)&p_xh,   g_xh);
    cudaGetSymbolAddress((void**)&p_qkvh, g_qkvh);
    cudaGetSymbolAddress((void**)&p_ath,  g_ath);
    cudaGetSymbolAddress((void**)&p_hh,   g_hh);
    cudaGetSymbolAddress((void**)&p_xfh,  g_xfh);
    cudaGetSymbolAddress((void**)&p_inwh, g_inwh);
    cudaGetSymbolAddress((void**)&p_outwh,g_outwh);
    cudaGetSymbolAddress((void**)&p_headh,g_headh);
    cudaGetSymbolAddress((void**)&p_w1h,  g_w1h);
    cudaGetSymbolAddress((void**)&p_w2h,  g_w2h);

    // ---- routers + combined W2 bias (x-independent) ----
    for (int l = 0; l < Lnum; l++)
        k_router<<<1, 256>>>(c_states, router_w + (long)l * En * CDm,
                             router_b + (long)l * En, l);
    {
        dim3 gb(Lnum, Dm / 256);
        k_cbias<<<gb, 256>>>(e_b2);
    }

    // ---- weight conversions ----
    {
        long n;
        n = (long)Lnum * 3 * Dm * Dm;
        k_half<<<(unsigned)((n/4 + 255) / 256), 256>>>(in_w, p_inwh, n);
        n = (long)Lnum * Dm * Dm;
        k_half<<<(unsigned)((n/4 + 255) / 256), 256>>>(out_w, p_outwh, n);
        n = (long)Vv * Dm;
        k_half<<<(unsigned)((n/4 + 255) / 256), 256>>>(head_w, p_headh, n);
        long ne = (long)Fm * Dm;
        unsigned ge = (unsigned)((ne/4 + 255) / 256);
        for (int l = 0; l < Lnum; l++)
            for (int s = 0; s < 2; s++) {
                int sidx = l*2 + s;
                k_half_exp<<<ge, 256>>>(e_w1 + (long)l * En * Fm * Dm,
                                        p_w1h + (long)sidx * ne, ne, sidx);
                k_half_exp2<<<ge, 256>>>(e_w2 + (long)l * En * Dm * Fm,
                                         p_w2h + (long)l * Dm * 2 * Fm, sidx, s);
            }
    }

    k_embed<<<BT, 256>>>(tokens, embed_w, pos_w);

    dim3 blk(256);
    for (int l = 0; l < Lnum; l++) {
        {   // QKV projection -> fp16 qkv
            dim3 grid(BT / BM, (3 * Dm) / BN);
            k_gemm5<<<grid, blk, GEMM_SMEM>>>(
                p_xh, p_inwh + (long)l * 3 * Dm * Dm,
                in_b + (long)l * 3 * Dm,
                nullptr, p_qkvh,
                BT, 3 * Dm, Dm, l, 0);
        }
        {   // flash attention -> fp16 attn
            dim3 grid(Tn / AQT, Hn, Bn);
            k_attn_fa4<<<grid, 256, ATT_SMEM>>>();
        }
        {   // output projection -> fp32 tmp
            dim3 grid(BT / BM, Dm / BN);
            k_gemm5<<<grid, blk, GEMM_SMEM>>>(
                p_ath, p_outwh + (long)l * Dm * Dm,
                out_b + (long)l * Dm,
                p_tmp, nullptr,
                BT, Dm, Dm, l, 0);
        }
        k_add_ln<<<BT, 256>>>(p_x, p_tmp, ln_a_g + l * Dm, ln_a_b + l * Dm,
                              p_x, p_xh);

        {   // fused MoE W1 (both experts): N = 2*Fm, GELU+gate in epilogue
            dim3 grid(BT / BM, (2 * Fm) / BN);
            k_gemm5<<<grid, blk, GEMM_SMEM>>>(
                p_xh, p_w1h + (long)l * 2 * Fm * Dm,
                e_b1 + (long)l * En * Fm,
                nullptr, p_hh,
                BT, 2 * Fm, Dm, l, 16);
        }
        {   // fused MoE W2: K = 2*Fm, combined bias, single pass
            dim3 grid(BT / BM, Dm / BN);
            k_gemm5<<<grid, blk, GEMM_SMEM>>>(
                p_hh, p_w2h + (long)l * Dm * 2 * Fm,
                p_cb2 + (long)l * Dm,
                p_moe, nullptr,
                BT, Dm, 2 * Fm, l, 0);
        }
        k_add_ln<<<BT, 256>>>(p_x, p_moe, ln_m_g + l * Dm, ln_m_b + l * Dm,
                              p_x, p_xh);
    }

    k_add_ln<<<BT, 256>>>(p_x, nullptr, ln_f_g, ln_f_b, p_xf, p_xfh);

    {   // LM head: streaming fp32 output (odd N -> scalar streaming stores)
        dim3 grid(BT / BM, (Vv + BN - 1) / BN);
        k_gemm5<<<grid, blk, GEMM_SMEM>>>(
            p_xfh, p_headh, nullptr,
            out, nullptr,
            BT, Vv, Dm, 0, 32);
    }
}